// round 12
// baseline (speedup 1.0000x reference)
#include <cuda_runtime.h>
#include <cuda_fp16.h>
#include <cstdint>

#define N_NODES 100000
#define N_EDGES 1600000
#define HC 128            // HEADS * OUT_CH
#define HEADS 4
#define OUT_CH 32
#define EDGE_CH 32
#define SCAN_BLK 1024
#define SCAN_NB ((N_NODES + SCAN_BLK - 1) / SCAN_BLK)   // 98

__constant__ float c_neg_slope = 0.2f;

// ---------------- scratch (static device globals; no allocation) ----------------
__device__ __half g_xlh[(size_t)N_NODES * HC];  // 25.6 MB projected node features (fp16)
__device__ float  g_al[N_NODES * HEADS];        // alpha_l per node/head
__device__ float  g_ar[N_NODES * HEADS];        // alpha_r per node/head
__device__ float  g_we[HC];                     // folded We^T * att_e  [H][32]
__device__ float4 g_denom[N_NODES];             // softmax denominators (sum of ex)
__device__ int    g_hist[N_NODES];              // in-degree histogram
__device__ int    g_offs[N_NODES];              // CSR start offsets (exclusive scan)
__device__ int    g_cursor[N_NODES];            // scatter cursors
__device__ int    g_bsum[SCAN_NB];              // scan block sums
__device__ int    g_csr_src[N_EDGES];           // dst-sorted source node ids
__device__ float4 g_csr_ex[N_EDGES];            // dst-sorted UNnormalized exp(logit)

// vectorized 16B global reduction (sm_90+)
__device__ __forceinline__ void red_add_v4(float4* p, float4 v) {
    asm volatile("red.global.add.v4.f32 [%0], {%1, %2, %3, %4};"
                 :: "l"(p), "f"(v.x), "f"(v.y), "f"(v.z), "f"(v.w)
                 : "memory");
}

// ---------------- zero hist + denom ----------------
__global__ void k_zero() {
    int idx = blockIdx.x * blockDim.x + threadIdx.x;
    if (idx < N_NODES * HEADS) ((float*)g_denom)[idx] = 0.0f;
    if (idx < N_NODES) g_hist[idx] = 0;
}

// ---------------- fold We with att_e  ->  g_we[h*32+k] ----------------
__global__ void k_wepre(const float* __restrict__ We, const float* __restrict__ att_e) {
    int t = threadIdx.x;           // 0..127  = h*32 + k
    int h = t >> 5, k = t & 31;
    float s = 0.0f;
#pragma unroll
    for (int c = 0; c < OUT_CH; c++)
        s += We[(h * OUT_CH + c) * EDGE_CH + k] * att_e[h * OUT_CH + c];
    g_we[t] = s;
}

// ---------------- in-degree histogram (dst only, int4 vectorized) ----------------
__global__ void k_hist(const int* __restrict__ ei) {
    int i = blockIdx.x * blockDim.x + threadIdx.x;   // quad index
    if (i * 4 >= N_EDGES) return;
    int4 d = ((const int4*)(ei + N_EDGES))[i];
    atomicAdd(&g_hist[d.x], 1);
    atomicAdd(&g_hist[d.y], 1);
    atomicAdd(&g_hist[d.z], 1);
    atomicAdd(&g_hist[d.w], 1);
}

// ---------------- xl = x @ Wl^T (fp16 store), plus alpha_l / alpha_r (fp32) ----------------
__global__ void k_gemm(const float* __restrict__ x, const float* __restrict__ Wl,
                       const float* __restrict__ att_l, const float* __restrict__ att_r) {
    __shared__ float xs[8][HC];
    const int j    = threadIdx.x;       // 0..127 output column
    const int lane = j & 31;
    const int w    = j >> 5;            // head index
    const float al_w = att_l[j];
    const float ar_w = att_r[j];
    const float4* __restrict__ Wrow = (const float4*)(Wl + (size_t)j * HC); // 32 float4

    for (int base = blockIdx.x * 8; base < N_NODES; base += gridDim.x * 8) {
        __syncthreads();
        {
            const float4* src = (const float4*)(x + (size_t)base * HC);
            ((float4*)xs)[j]       = src[j];
            ((float4*)xs)[j + 128] = src[j + 128];
        }
        __syncthreads();

        float acc[8];
#pragma unroll
        for (int i = 0; i < 8; i++) acc[i] = 0.f;
#pragma unroll 4
        for (int k4 = 0; k4 < HC / 4; k4++) {
            float4 wv = Wrow[k4];
#pragma unroll
            for (int i = 0; i < 8; i++) {
                float4 xv = ((const float4*)xs[i])[k4];
                acc[i] += wv.x * xv.x + wv.y * xv.y + wv.z * xv.z + wv.w * xv.w;
            }
        }
#pragma unroll
        for (int i = 0; i < 8; i++) {
            // fp16 store (alphas stay fp32 from the same fp32 accumulator)
            g_xlh[(size_t)(base + i) * HC + j] = __float2half_rn(acc[i]);
            float pl = acc[i] * al_w;
            float pr = acc[i] * ar_w;
#pragma unroll
            for (int off = 16; off; off >>= 1) {
                pl += __shfl_xor_sync(0xffffffffu, pl, off);
                pr += __shfl_xor_sync(0xffffffffu, pr, off);
            }
            if (lane == 0) {
                g_al[(base + i) * HEADS + w] = pl;
                g_ar[(base + i) * HEADS + w] = pr;
            }
        }
    }
}

// ---------------- scan kernels: exclusive prefix over g_hist -> g_offs ----------------
__global__ void k_scan1() {
    __shared__ int wsum[32];
    int i = blockIdx.x * SCAN_BLK + threadIdx.x;
    int lane = threadIdx.x & 31, wid = threadIdx.x >> 5;
    int v = (i < N_NODES) ? g_hist[i] : 0;
    int inc = v;
#pragma unroll
    for (int off = 1; off < 32; off <<= 1) {
        int t = __shfl_up_sync(0xffffffffu, inc, off);
        if (lane >= off) inc += t;
    }
    if (lane == 31) wsum[wid] = inc;
    __syncthreads();
    if (wid == 0) {
        int s = wsum[lane];
#pragma unroll
        for (int off = 1; off < 32; off <<= 1) {
            int t = __shfl_up_sync(0xffffffffu, s, off);
            if (lane >= off) s += t;
        }
        wsum[lane] = s;
    }
    __syncthreads();
    int base = (wid > 0) ? wsum[wid - 1] : 0;
    if (i < N_NODES) g_offs[i] = base + inc - v;
    if (threadIdx.x == SCAN_BLK - 1) g_bsum[blockIdx.x] = base + inc;
}

__global__ void k_scan2() {   // single block, scan SCAN_NB (=98) block totals, exclusive
    __shared__ int wsum[4];
    int lane = threadIdx.x & 31, wid = threadIdx.x >> 5;
    int v = (threadIdx.x < SCAN_NB) ? g_bsum[threadIdx.x] : 0;
    int inc = v;
#pragma unroll
    for (int off = 1; off < 32; off <<= 1) {
        int t = __shfl_up_sync(0xffffffffu, inc, off);
        if (lane >= off) inc += t;
    }
    if (lane == 31) wsum[wid] = inc;
    __syncthreads();
    int base = 0;
    for (int w = 0; w < wid; w++) base += wsum[w];
    if (threadIdx.x < SCAN_NB) g_bsum[threadIdx.x] = base + inc - v;
}

__global__ void k_scan3() {   // apply block offsets; init cursor = offs
    int i = blockIdx.x * SCAN_BLK + threadIdx.x;
    if (i < N_NODES) {
        int o = g_offs[i] + g_bsum[blockIdx.x];
        g_offs[i]   = o;
        g_cursor[i] = o;
    }
}

// ---------------- fused: logits + leaky-relu + exp + denom + CSR scatter ----------------
__global__ void k_logits(const float* __restrict__ edge_attr, const int* __restrict__ ei) {
    __shared__ float we_s[HC];
    if (threadIdx.x < HC) we_s[threadIdx.x] = g_we[threadIdx.x];
    __syncthreads();

    int e = blockIdx.x * blockDim.x + threadIdx.x;
    if (e >= N_EDGES) return;

    const float4* __restrict__ row = (const float4*)(edge_attr + (size_t)e * EDGE_CH);
    const float4* w0 = (const float4*)(we_s);
    const float4* w1 = (const float4*)(we_s + 32);
    const float4* w2 = (const float4*)(we_s + 64);
    const float4* w3 = (const float4*)(we_s + 96);
    float p0 = 0.f, p1 = 0.f, p2 = 0.f, p3 = 0.f;
#pragma unroll
    for (int i = 0; i < 8; i++) {
        float4 v = row[i];
        float4 a0 = w0[i], a1 = w1[i], a2 = w2[i], a3 = w3[i];
        p0 += v.x * a0.x + v.y * a0.y + v.z * a0.z + v.w * a0.w;
        p1 += v.x * a1.x + v.y * a1.y + v.z * a1.z + v.w * a1.w;
        p2 += v.x * a2.x + v.y * a2.y + v.z * a2.z + v.w * a2.w;
        p3 += v.x * a3.x + v.y * a3.y + v.z * a3.z + v.w * a3.w;
    }
    int src = ei[e];
    int dst = ei[N_EDGES + e];
    float4 al = ((const float4*)g_al)[src];
    float4 ar = ((const float4*)g_ar)[dst];
    float a0 = al.x + ar.x + p0;
    float a1 = al.y + ar.y + p1;
    float a2 = al.z + ar.z + p2;
    float a3 = al.w + ar.w + p3;
    a0 = (a0 > 0.f) ? a0 : c_neg_slope * a0;
    a1 = (a1 > 0.f) ? a1 : c_neg_slope * a1;
    a2 = (a2 > 0.f) ? a2 : c_neg_slope * a2;
    a3 = (a3 > 0.f) ? a3 : c_neg_slope * a3;
    float4 ex = make_float4(__expf(a0), __expf(a1), __expf(a2), __expf(a3));
    int pos = atomicAdd(&g_cursor[dst], 1);
    g_csr_src[pos] = src;
    g_csr_ex[pos]  = ex;
    red_add_v4(&g_denom[dst], ex);
}

// ---------------- gather aggregation: one warp per dst node (fp16 gathers, fp32 math) ----------------
// lane's 4 channels = one uint2 (2 x half2) -> 256B coalesced row per edge (half the traffic).
__global__ void k_agg(const float* __restrict__ bias, float* __restrict__ out) {
    const int lane = threadIdx.x & 31;
    const int h    = lane >> 3;                 // head owning this lane's 4 channels
    int node = blockIdx.x * (blockDim.x >> 5) + (threadIdx.x >> 5);
    if (node >= N_NODES) return;

    int beg = g_offs[node];
    int end = g_cursor[node];                   // start + degree
    const uint2* __restrict__ xlv = (const uint2*)g_xlh;   // row = 32 uint2 (128 halves)
    float4 acc = make_float4(0.f, 0.f, 0.f, 0.f);

    int pos = beg;
    for (; pos + 3 < end; pos += 4) {
        int s0 = g_csr_src[pos];
        int s1 = g_csr_src[pos + 1];
        int s2 = g_csr_src[pos + 2];
        int s3 = g_csr_src[pos + 3];
        float a0 = ((const float*)g_csr_ex)[(size_t)pos * 4 + h];
        float a1 = ((const float*)g_csr_ex)[(size_t)(pos + 1) * 4 + h];
        float a2 = ((const float*)g_csr_ex)[(size_t)(pos + 2) * 4 + h];
        float a3 = ((const float*)g_csr_ex)[(size_t)(pos + 3) * 4 + h];
        uint2 u0 = xlv[(size_t)s0 * 32 + lane];
        uint2 u1 = xlv[(size_t)s1 * 32 + lane];
        uint2 u2 = xlv[(size_t)s2 * 32 + lane];
        uint2 u3 = xlv[(size_t)s3 * 32 + lane];
        float2 f0a = __half22float2(*(const __half2*)&u0.x);
        float2 f0b = __half22float2(*(const __half2*)&u0.y);
        float2 f1a = __half22float2(*(const __half2*)&u1.x);
        float2 f1b = __half22float2(*(const __half2*)&u1.y);
        float2 f2a = __half22float2(*(const __half2*)&u2.x);
        float2 f2b = __half22float2(*(const __half2*)&u2.y);
        float2 f3a = __half22float2(*(const __half2*)&u3.x);
        float2 f3b = __half22float2(*(const __half2*)&u3.y);
        acc.x += a0 * f0a.x + a1 * f1a.x + a2 * f2a.x + a3 * f3a.x;
        acc.y += a0 * f0a.y + a1 * f1a.y + a2 * f2a.y + a3 * f3a.y;
        acc.z += a0 * f0b.x + a1 * f1b.x + a2 * f2b.x + a3 * f3b.x;
        acc.w += a0 * f0b.y + a1 * f1b.y + a2 * f2b.y + a3 * f3b.y;
    }
    for (; pos < end; pos++) {
        int s0 = g_csr_src[pos];
        float a0 = ((const float*)g_csr_ex)[(size_t)pos * 4 + h];
        uint2 u0 = xlv[(size_t)s0 * 32 + lane];
        float2 f0a = __half22float2(*(const __half2*)&u0.x);
        float2 f0b = __half22float2(*(const __half2*)&u0.y);
        acc.x += a0 * f0a.x; acc.y += a0 * f0a.y;
        acc.z += a0 * f0b.x; acc.w += a0 * f0b.y;
    }
    float inv = 1.0f / (((const float*)g_denom)[(size_t)node * 4 + h] + 1e-16f);
    float4 b = ((const float4*)bias)[lane];
    acc.x = acc.x * inv + b.x;
    acc.y = acc.y * inv + b.y;
    acc.z = acc.z * inv + b.z;
    acc.w = acc.w * inv + b.w;
    ((float4*)out)[(size_t)node * 32 + lane] = acc;
}

// ---------------- launch: R9 schedule (gemm || edge-prep chain) ----------------
extern "C" void kernel_launch(void* const* d_in, const int* in_sizes, int n_in,
                              void* d_out, int out_size) {
    const float* x         = (const float*)d_in[0];
    const float* edge_attr = (const float*)d_in[1];
    const float* Wl        = (const float*)d_in[2];
    const float* We        = (const float*)d_in[3];
    const float* att_l     = (const float*)d_in[4];
    const float* att_r     = (const float*)d_in[5];
    const float* att_e     = (const float*)d_in[6];
    const float* bias      = (const float*)d_in[7];
    const int*   ei        = (const int*)d_in[8];
    float* out = (float*)d_out;

    cudaStream_t sA, sB;
    cudaStreamCreateWithFlags(&sA, cudaStreamNonBlocking);
    cudaStreamCreateWithFlags(&sB, cudaStreamNonBlocking);
    cudaEvent_t evRoot, evA, evB;
    cudaEventCreateWithFlags(&evRoot, cudaEventDisableTiming);
    cudaEventCreateWithFlags(&evA,    cudaEventDisableTiming);
    cudaEventCreateWithFlags(&evB,    cudaEventDisableTiming);

    cudaEventRecord(evRoot, 0);
    cudaStreamWaitEvent(sA, evRoot, 0);
    cudaStreamWaitEvent(sB, evRoot, 0);

    // Branch A (sA): edge-prep chain — zero, hist, scans
    k_zero <<<(N_NODES * HEADS + 255) / 256, 256, 0, sA>>>();
    k_hist <<<(N_EDGES / 4 + 255) / 256, 256, 0, sA>>>(ei);
    k_scan1<<<SCAN_NB, SCAN_BLK, 0, sA>>>();
    k_scan2<<<1, 128, 0, sA>>>();
    k_scan3<<<SCAN_NB, SCAN_BLK, 0, sA>>>();
    cudaEventRecord(evA, sA);

    // Branch B (sB): tiny weight fold
    k_wepre<<<1, 128, 0, sB>>>(We, att_e);
    cudaEventRecord(evB, sB);

    // Main stream: FMA-bound GEMM overlaps branch A's L2/atomic work
    k_gemm<<<2368, 128>>>(x, Wl, att_l, att_r);

    // join
    cudaStreamWaitEvent(0, evA, 0);
    cudaStreamWaitEvent(0, evB, 0);

    k_logits<<<(N_EDGES + 255) / 256, 256>>>(edge_attr, ei);
    k_agg<<<(N_NODES * 32 + 255) / 256, 256>>>(bias, out);

    cudaEventDestroy(evRoot);
    cudaEventDestroy(evA);
    cudaEventDestroy(evB);
    cudaStreamDestroy(sA);
    cudaStreamDestroy(sB);
}

// round 13
// speedup vs baseline: 1.0048x; 1.0048x over previous
#include <cuda_runtime.h>
#include <cstdint>

#define N_NODES 100000
#define N_EDGES 1600000
#define HC 128            // HEADS * OUT_CH
#define HEADS 4
#define OUT_CH 32
#define EDGE_CH 32
#define SCAN_BLK 1024
#define SCAN_NB ((N_NODES + SCAN_BLK - 1) / SCAN_BLK)   // 98

__constant__ float c_neg_slope = 0.2f;

// ---------------- scratch (static device globals; no allocation) ----------------
__device__ float  g_xl[(size_t)N_NODES * HC];   // 51.2 MB projected node features
__device__ float  g_al[N_NODES * HEADS];        // alpha_l per node/head
__device__ float  g_ar[N_NODES * HEADS];        // alpha_r per node/head
__device__ float  g_we[HC];                     // folded We^T * att_e  [H][32]
__device__ float4 g_denom[N_NODES];             // softmax denominators (sum of ex)
__device__ int    g_hist[N_NODES];              // in-degree histogram
__device__ int    g_offs[N_NODES];              // CSR start offsets (exclusive scan)
__device__ int    g_cursor[N_NODES];            // scatter cursors
__device__ int    g_bsum[SCAN_NB];              // scan block sums
__device__ int    g_csr_src[N_EDGES];           // dst-sorted source node ids
__device__ float4 g_csr_ex[N_EDGES];            // dst-sorted UNnormalized exp(logit)

// vectorized 16B global reduction (sm_90+)
__device__ __forceinline__ void red_add_v4(float4* p, float4 v) {
    asm volatile("red.global.add.v4.f32 [%0], {%1, %2, %3, %4};"
                 :: "l"(p), "f"(v.x), "f"(v.y), "f"(v.z), "f"(v.w)
                 : "memory");
}

// ---------------- zero hist + denom ----------------
__global__ void k_zero() {
    int idx = blockIdx.x * blockDim.x + threadIdx.x;
    if (idx < N_NODES * HEADS) ((float*)g_denom)[idx] = 0.0f;
    if (idx < N_NODES) g_hist[idx] = 0;
}

// ---------------- fold We with att_e  ->  g_we[h*32+k] ----------------
__global__ void k_wepre(const float* __restrict__ We, const float* __restrict__ att_e) {
    int t = threadIdx.x;           // 0..127  = h*32 + k
    int h = t >> 5, k = t & 31;
    float s = 0.0f;
#pragma unroll
    for (int c = 0; c < OUT_CH; c++)
        s += We[(h * OUT_CH + c) * EDGE_CH + k] * att_e[h * OUT_CH + c];
    g_we[t] = s;
}

// ---------------- in-degree histogram (dst only, int4 vectorized) ----------------
__global__ void k_hist(const int* __restrict__ ei) {
    int i = blockIdx.x * blockDim.x + threadIdx.x;   // quad index
    if (i * 4 >= N_EDGES) return;
    int4 d = ((const int4*)(ei + N_EDGES))[i];
    atomicAdd(&g_hist[d.x], 1);
    atomicAdd(&g_hist[d.y], 1);
    atomicAdd(&g_hist[d.z], 1);
    atomicAdd(&g_hist[d.w], 1);
}

// ---------------- xl = x @ Wl^T, plus alpha_l / alpha_r (8-node tiles) ----------------
__global__ void k_gemm(const float* __restrict__ x, const float* __restrict__ Wl,
                       const float* __restrict__ att_l, const float* __restrict__ att_r) {
    __shared__ float xs[8][HC];
    const int j    = threadIdx.x;       // 0..127 output column
    const int lane = j & 31;
    const int w    = j >> 5;            // head index
    const float al_w = att_l[j];
    const float ar_w = att_r[j];
    const float4* __restrict__ Wrow = (const float4*)(Wl + (size_t)j * HC); // 32 float4

    for (int base = blockIdx.x * 8; base < N_NODES; base += gridDim.x * 8) {
        __syncthreads();
        {
            const float4* src = (const float4*)(x + (size_t)base * HC);
            ((float4*)xs)[j]       = src[j];
            ((float4*)xs)[j + 128] = src[j + 128];
        }
        __syncthreads();

        float acc[8];
#pragma unroll
        for (int i = 0; i < 8; i++) acc[i] = 0.f;
#pragma unroll 4
        for (int k4 = 0; k4 < HC / 4; k4++) {
            float4 wv = Wrow[k4];
#pragma unroll
            for (int i = 0; i < 8; i++) {
                float4 xv = ((const float4*)xs[i])[k4];
                acc[i] += wv.x * xv.x + wv.y * xv.y + wv.z * xv.z + wv.w * xv.w;
            }
        }
#pragma unroll
        for (int i = 0; i < 8; i++) {
            g_xl[(size_t)(base + i) * HC + j] = acc[i];
            float pl = acc[i] * al_w;
            float pr = acc[i] * ar_w;
#pragma unroll
            for (int off = 16; off; off >>= 1) {
                pl += __shfl_xor_sync(0xffffffffu, pl, off);
                pr += __shfl_xor_sync(0xffffffffu, pr, off);
            }
            if (lane == 0) {
                g_al[(base + i) * HEADS + w] = pl;
                g_ar[(base + i) * HEADS + w] = pr;
            }
        }
    }
}

// ---------------- scan kernels: exclusive prefix over g_hist -> g_offs ----------------
__global__ void k_scan1() {
    __shared__ int wsum[32];
    int i = blockIdx.x * SCAN_BLK + threadIdx.x;
    int lane = threadIdx.x & 31, wid = threadIdx.x >> 5;
    int v = (i < N_NODES) ? g_hist[i] : 0;
    int inc = v;
#pragma unroll
    for (int off = 1; off < 32; off <<= 1) {
        int t = __shfl_up_sync(0xffffffffu, inc, off);
        if (lane >= off) inc += t;
    }
    if (lane == 31) wsum[wid] = inc;
    __syncthreads();
    if (wid == 0) {
        int s = wsum[lane];
#pragma unroll
        for (int off = 1; off < 32; off <<= 1) {
            int t = __shfl_up_sync(0xffffffffu, s, off);
            if (lane >= off) s += t;
        }
        wsum[lane] = s;
    }
    __syncthreads();
    int base = (wid > 0) ? wsum[wid - 1] : 0;
    if (i < N_NODES) g_offs[i] = base + inc - v;
    if (threadIdx.x == SCAN_BLK - 1) g_bsum[blockIdx.x] = base + inc;
}

__global__ void k_scan2() {   // single block, scan SCAN_NB (=98) block totals, exclusive
    __shared__ int wsum[4];
    int lane = threadIdx.x & 31, wid = threadIdx.x >> 5;
    int v = (threadIdx.x < SCAN_NB) ? g_bsum[threadIdx.x] : 0;
    int inc = v;
#pragma unroll
    for (int off = 1; off < 32; off <<= 1) {
        int t = __shfl_up_sync(0xffffffffu, inc, off);
        if (lane >= off) inc += t;
    }
    if (lane == 31) wsum[wid] = inc;
    __syncthreads();
    int base = 0;
    for (int w = 0; w < wid; w++) base += wsum[w];
    if (threadIdx.x < SCAN_NB) g_bsum[threadIdx.x] = base + inc - v;
}

__global__ void k_scan3() {   // apply block offsets; init cursor = offs
    int i = blockIdx.x * SCAN_BLK + threadIdx.x;
    if (i < N_NODES) {
        int o = g_offs[i] + g_bsum[blockIdx.x];
        g_offs[i]   = o;
        g_cursor[i] = o;
    }
}

// ---------------- fused: logits + leaky-relu + exp + denom + CSR scatter ----------------
// index loads + cursor atomic hoisted ABOVE the dot product: ATOMG latency overlaps FMA chain.
__global__ void k_logits(const float* __restrict__ edge_attr, const int* __restrict__ ei) {
    __shared__ float we_s[HC];
    if (threadIdx.x < HC) we_s[threadIdx.x] = g_we[threadIdx.x];
    __syncthreads();

    int e = blockIdx.x * blockDim.x + threadIdx.x;
    if (e >= N_EDGES) return;

    // hoisted: slot reservation + alpha gathers issue before the dot-product chain
    int src = ei[e];
    int dst = ei[N_EDGES + e];
    int pos = atomicAdd(&g_cursor[dst], 1);
    float4 al = ((const float4*)g_al)[src];
    float4 ar = ((const float4*)g_ar)[dst];

    const float4* __restrict__ row = (const float4*)(edge_attr + (size_t)e * EDGE_CH);
    const float4* w0 = (const float4*)(we_s);
    const float4* w1 = (const float4*)(we_s + 32);
    const float4* w2 = (const float4*)(we_s + 64);
    const float4* w3 = (const float4*)(we_s + 96);
    float p0 = 0.f, p1 = 0.f, p2 = 0.f, p3 = 0.f;
#pragma unroll
    for (int i = 0; i < 8; i++) {
        float4 v = row[i];
        float4 a0 = w0[i], a1 = w1[i], a2 = w2[i], a3 = w3[i];
        p0 += v.x * a0.x + v.y * a0.y + v.z * a0.z + v.w * a0.w;
        p1 += v.x * a1.x + v.y * a1.y + v.z * a1.z + v.w * a1.w;
        p2 += v.x * a2.x + v.y * a2.y + v.z * a2.z + v.w * a2.w;
        p3 += v.x * a3.x + v.y * a3.y + v.z * a3.z + v.w * a3.w;
    }
    float a0 = al.x + ar.x + p0;
    float a1 = al.y + ar.y + p1;
    float a2 = al.z + ar.z + p2;
    float a3 = al.w + ar.w + p3;
    a0 = (a0 > 0.f) ? a0 : c_neg_slope * a0;
    a1 = (a1 > 0.f) ? a1 : c_neg_slope * a1;
    a2 = (a2 > 0.f) ? a2 : c_neg_slope * a2;
    a3 = (a3 > 0.f) ? a3 : c_neg_slope * a3;
    float4 ex = make_float4(__expf(a0), __expf(a1), __expf(a2), __expf(a3));
    g_csr_src[pos] = src;
    g_csr_ex[pos]  = ex;
    red_add_v4(&g_denom[dst], ex);
}

// ---------------- gather aggregation: one warp per dst node (R4 body, fp32) ----------------
__global__ void k_agg(const float* __restrict__ bias, float* __restrict__ out) {
    const int lane = threadIdx.x & 31;
    const int h    = lane >> 3;                 // head owning this lane's float4
    int node = blockIdx.x * (blockDim.x >> 5) + (threadIdx.x >> 5);
    if (node >= N_NODES) return;

    int beg = g_offs[node];
    int end = g_cursor[node];                   // start + degree
    float4 acc = make_float4(0.f, 0.f, 0.f, 0.f);

    int pos = beg;
    for (; pos + 3 < end; pos += 4) {
        int s0 = g_csr_src[pos];
        int s1 = g_csr_src[pos + 1];
        int s2 = g_csr_src[pos + 2];
        int s3 = g_csr_src[pos + 3];
        float a0 = ((const float*)g_csr_ex)[(size_t)pos * 4 + h];
        float a1 = ((const float*)g_csr_ex)[(size_t)(pos + 1) * 4 + h];
        float a2 = ((const float*)g_csr_ex)[(size_t)(pos + 2) * 4 + h];
        float a3 = ((const float*)g_csr_ex)[(size_t)(pos + 3) * 4 + h];
        float4 v0 = ((const float4*)g_xl)[(size_t)s0 * 32 + lane];
        float4 v1 = ((const float4*)g_xl)[(size_t)s1 * 32 + lane];
        float4 v2 = ((const float4*)g_xl)[(size_t)s2 * 32 + lane];
        float4 v3 = ((const float4*)g_xl)[(size_t)s3 * 32 + lane];
        acc.x += a0 * v0.x + a1 * v1.x + a2 * v2.x + a3 * v3.x;
        acc.y += a0 * v0.y + a1 * v1.y + a2 * v2.y + a3 * v3.y;
        acc.z += a0 * v0.z + a1 * v1.z + a2 * v2.z + a3 * v3.z;
        acc.w += a0 * v0.w + a1 * v1.w + a2 * v2.w + a3 * v3.w;
    }
    for (; pos < end; pos++) {
        int s0 = g_csr_src[pos];
        float a0 = ((const float*)g_csr_ex)[(size_t)pos * 4 + h];
        float4 v0 = ((const float4*)g_xl)[(size_t)s0 * 32 + lane];
        acc.x += a0 * v0.x; acc.y += a0 * v0.y; acc.z += a0 * v0.z; acc.w += a0 * v0.w;
    }
    float inv = 1.0f / (((const float*)g_denom)[(size_t)node * 4 + h] + 1e-16f);
    float4 b = ((const float4*)bias)[lane];
    acc.x = acc.x * inv + b.x;
    acc.y = acc.y * inv + b.y;
    acc.z = acc.z * inv + b.z;
    acc.w = acc.w * inv + b.w;
    ((float4*)out)[(size_t)node * 32 + lane] = acc;
}

// ---------------- launch: R9 schedule; k_gemm enqueued 4th so ncu profiles it ----------------
extern "C" void kernel_launch(void* const* d_in, const int* in_sizes, int n_in,
                              void* d_out, int out_size) {
    const float* x         = (const float*)d_in[0];
    const float* edge_attr = (const float*)d_in[1];
    const float* Wl        = (const float*)d_in[2];
    const float* We        = (const float*)d_in[3];
    const float* att_l     = (const float*)d_in[4];
    const float* att_r     = (const float*)d_in[5];
    const float* att_e     = (const float*)d_in[6];
    const float* bias      = (const float*)d_in[7];
    const int*   ei        = (const int*)d_in[8];
    float* out = (float*)d_out;

    cudaStream_t sA, sB;
    cudaStreamCreateWithFlags(&sA, cudaStreamNonBlocking);
    cudaStreamCreateWithFlags(&sB, cudaStreamNonBlocking);
    cudaEvent_t evRoot, evA, evB;
    cudaEventCreateWithFlags(&evRoot, cudaEventDisableTiming);
    cudaEventCreateWithFlags(&evA,    cudaEventDisableTiming);
    cudaEventCreateWithFlags(&evB,    cudaEventDisableTiming);

    cudaEventRecord(evRoot, 0);
    cudaStreamWaitEvent(sA, evRoot, 0);
    cudaStreamWaitEvent(sB, evRoot, 0);

    // Branch A part 1 (sA): launches 0-2
    k_zero <<<(N_NODES * HEADS + 255) / 256, 256, 0, sA>>>();
    k_hist <<<(N_EDGES / 4 + 255) / 256, 256, 0, sA>>>(ei);
    k_scan1<<<SCAN_NB, SCAN_BLK, 0, sA>>>();

    // Main stream: GEMM enqueued as launch #3 (4th) -> lands in the ncu capture slot
    k_gemm<<<2368, 128>>>(x, Wl, att_l, att_r);

    // Branch A part 2 (sA): stream ordering within sA is preserved
    k_scan2<<<1, 128, 0, sA>>>();
    k_scan3<<<SCAN_NB, SCAN_BLK, 0, sA>>>();
    cudaEventRecord(evA, sA);

    // Branch B (sB): tiny weight fold
    k_wepre<<<1, 128, 0, sB>>>(We, att_e);
    cudaEventRecord(evB, sB);

    // join
    cudaStreamWaitEvent(0, evA, 0);
    cudaStreamWaitEvent(0, evB, 0);

    k_logits<<<(N_EDGES + 255) / 256, 256>>>(edge_attr, ei);
    k_agg<<<(N_NODES * 32 + 255) / 256, 256>>>(bias, out);

    cudaEventDestroy(evRoot);
    cudaEventDestroy(evA);
    cudaEventDestroy(evB);
    cudaStreamDestroy(sA);
    cudaStreamDestroy(sB);
}

// round 14
// speedup vs baseline: 1.3233x; 1.3171x over previous
#include <cuda_runtime.h>
#include <cstdint>

#define N_NODES 100000
#define N_EDGES 1600000
#define HC 128            // HEADS * OUT_CH
#define HEADS 4
#define OUT_CH 32
#define EDGE_CH 32
#define SCAN_BLK 1024
#define SCAN_NB ((N_NODES + SCAN_BLK - 1) / SCAN_BLK)   // 98
#define GEMM_BLOCKS 296
#define GEMM_SMEM ((128 * 33 + 32 * 33) * 16)           // 84480 bytes

__constant__ float c_neg_slope = 0.2f;

// ---------------- scratch (static device globals; no allocation) ----------------
__device__ float  g_xl[(size_t)N_NODES * HC];   // 51.2 MB projected node features
__device__ float  g_al[N_NODES * HEADS];        // alpha_l per node/head
__device__ float  g_ar[N_NODES * HEADS];        // alpha_r per node/head
__device__ float  g_we[HC];                     // folded We^T * att_e  [H][32]
__device__ float4 g_denom[N_NODES];             // softmax denominators (sum of ex)
__device__ int    g_hist[N_NODES];              // in-degree histogram
__device__ int    g_offs[N_NODES];              // CSR start offsets (exclusive scan)
__device__ int    g_cursor[N_NODES];            // scatter cursors
__device__ int    g_bsum[SCAN_NB];              // scan block sums
__device__ int    g_csr_src[N_EDGES];           // dst-sorted source node ids
__device__ float4 g_csr_ex[N_EDGES];            // dst-sorted UNnormalized exp(logit)

// vectorized 16B global reduction (sm_90+)
__device__ __forceinline__ void red_add_v4(float4* p, float4 v) {
    asm volatile("red.global.add.v4.f32 [%0], {%1, %2, %3, %4};"
                 :: "l"(p), "f"(v.x), "f"(v.y), "f"(v.z), "f"(v.w)
                 : "memory");
}

// ---------------- zero hist + denom ----------------
__global__ void k_zero() {
    int idx = blockIdx.x * blockDim.x + threadIdx.x;
    if (idx < N_NODES * HEADS) ((float*)g_denom)[idx] = 0.0f;
    if (idx < N_NODES) g_hist[idx] = 0;
}

// ---------------- fold We with att_e  ->  g_we[h*32+k] ----------------
__global__ void k_wepre(const float* __restrict__ We, const float* __restrict__ att_e) {
    int t = threadIdx.x;           // 0..127  = h*32 + k
    int h = t >> 5, k = t & 31;
    float s = 0.0f;
#pragma unroll
    for (int c = 0; c < OUT_CH; c++)
        s += We[(h * OUT_CH + c) * EDGE_CH + k] * att_e[h * OUT_CH + c];
    g_we[t] = s;
}

// ---------------- in-degree histogram (dst only, int4 vectorized) ----------------
__global__ void k_hist(const int* __restrict__ ei) {
    int i = blockIdx.x * blockDim.x + threadIdx.x;   // quad index
    if (i * 4 >= N_EDGES) return;
    int4 d = ((const int4*)(ei + N_EDGES))[i];
    atomicAdd(&g_hist[d.x], 1);
    atomicAdd(&g_hist[d.y], 1);
    atomicAdd(&g_hist[d.z], 1);
    atomicAdd(&g_hist[d.w], 1);
}

// ---------------- register-blocked GEMM: xl = x @ Wl^T, fused alpha_l / alpha_r ----------------
// Thread tile 4 nodes x 8 cols; Wl fully staged in smem (33-float4 padded rows, conflict-free);
// per k4: 12 LDS.128 -> 128 FMA. Warp w == head w, alphas reduced via 2 shfls.
__global__ __launch_bounds__(128, 2) void k_gemm(const float* __restrict__ x,
                                                 const float* __restrict__ Wl,
                                                 const float* __restrict__ att_l,
                                                 const float* __restrict__ att_r) {
    extern __shared__ float4 smem4[];
    float4* ws4 = smem4;                 // [128 cols][33]  (32 used + 1 pad)
    float4* xs4 = smem4 + 128 * 33;      // [32 nodes][33]

    const int tid      = threadIdx.x;
    const int lane     = tid & 31;
    const int w        = tid >> 5;       // warp index == head
    const int tc_local = lane >> 3;      // 0..3
    const int tn       = lane & 7;       // 0..7 (node group)
    const int tc       = w * 4 + tc_local;  // 0..15 (col group of 8)

    float attl[8], attr[8];
#pragma unroll
    for (int i = 0; i < 8; i++) {
        attl[i] = att_l[tc * 8 + i];
        attr[i] = att_r[tc * 8 + i];
    }

    // stage all of Wl: 4096 float4, coalesced reads, conflict-free padded writes
    for (int idx = tid; idx < 128 * 32; idx += 128) {
        int col = idx >> 5, kq = idx & 31;
        ws4[col * 33 + kq] = ((const float4*)Wl)[idx];
    }

    for (int base = blockIdx.x * 32; base < N_NODES; base += gridDim.x * 32) {
        __syncthreads();    // xs4 free (and first-iter: ws4 staged)
        for (int idx = tid; idx < 32 * 32; idx += 128) {
            int nn = idx >> 5, kq = idx & 31;
            xs4[nn * 33 + kq] = ((const float4*)x)[(size_t)(base + nn) * 32 + kq];
        }
        __syncthreads();

        float acc[4][8];
#pragma unroll
        for (int n = 0; n < 4; n++)
#pragma unroll
            for (int i = 0; i < 8; i++) acc[n][i] = 0.f;

#pragma unroll 2
        for (int kq = 0; kq < 32; kq++) {
            float4 xv[4], wv[8];
#pragma unroll
            for (int n = 0; n < 4; n++) xv[n] = xs4[(tn * 4 + n) * 33 + kq];
#pragma unroll
            for (int i = 0; i < 8; i++) wv[i] = ws4[(tc * 8 + i) * 33 + kq];
#pragma unroll
            for (int n = 0; n < 4; n++)
#pragma unroll
                for (int i = 0; i < 8; i++)
                    acc[n][i] += xv[n].x * wv[i].x + xv[n].y * wv[i].y
                               + xv[n].z * wv[i].z + xv[n].w * wv[i].w;
        }

#pragma unroll
        for (int n = 0; n < 4; n++) {
            int node = base + tn * 4 + n;
            float4 lo = make_float4(acc[n][0], acc[n][1], acc[n][2], acc[n][3]);
            float4 hi = make_float4(acc[n][4], acc[n][5], acc[n][6], acc[n][7]);
            ((float4*)g_xl)[(size_t)node * 32 + tc * 2]     = lo;
            ((float4*)g_xl)[(size_t)node * 32 + tc * 2 + 1] = hi;
            float pl = 0.f, pr = 0.f;
#pragma unroll
            for (int i = 0; i < 8; i++) {
                pl += acc[n][i] * attl[i];
                pr += acc[n][i] * attr[i];
            }
            pl += __shfl_down_sync(0xffffffffu, pl, 16);
            pl += __shfl_down_sync(0xffffffffu, pl, 8);
            pr += __shfl_down_sync(0xffffffffu, pr, 16);
            pr += __shfl_down_sync(0xffffffffu, pr, 8);
            if (tc_local == 0) {
                g_al[node * HEADS + w] = pl;
                g_ar[node * HEADS + w] = pr;
            }
        }
    }
}

// ---------------- scan kernels: exclusive prefix over g_hist -> g_offs ----------------
__global__ void k_scan1() {
    __shared__ int wsum[32];
    int i = blockIdx.x * SCAN_BLK + threadIdx.x;
    int lane = threadIdx.x & 31, wid = threadIdx.x >> 5;
    int v = (i < N_NODES) ? g_hist[i] : 0;
    int inc = v;
#pragma unroll
    for (int off = 1; off < 32; off <<= 1) {
        int t = __shfl_up_sync(0xffffffffu, inc, off);
        if (lane >= off) inc += t;
    }
    if (lane == 31) wsum[wid] = inc;
    __syncthreads();
    if (wid == 0) {
        int s = wsum[lane];
#pragma unroll
        for (int off = 1; off < 32; off <<= 1) {
            int t = __shfl_up_sync(0xffffffffu, s, off);
            if (lane >= off) s += t;
        }
        wsum[lane] = s;
    }
    __syncthreads();
    int base = (wid > 0) ? wsum[wid - 1] : 0;
    if (i < N_NODES) g_offs[i] = base + inc - v;
    if (threadIdx.x == SCAN_BLK - 1) g_bsum[blockIdx.x] = base + inc;
}

__global__ void k_scan2() {   // single block, scan SCAN_NB (=98) block totals, exclusive
    __shared__ int wsum[4];
    int lane = threadIdx.x & 31, wid = threadIdx.x >> 5;
    int v = (threadIdx.x < SCAN_NB) ? g_bsum[threadIdx.x] : 0;
    int inc = v;
#pragma unroll
    for (int off = 1; off < 32; off <<= 1) {
        int t = __shfl_up_sync(0xffffffffu, inc, off);
        if (lane >= off) inc += t;
    }
    if (lane == 31) wsum[wid] = inc;
    __syncthreads();
    int base = 0;
    for (int w = 0; w < wid; w++) base += wsum[w];
    if (threadIdx.x < SCAN_NB) g_bsum[threadIdx.x] = base + inc - v;
}

__global__ void k_scan3() {   // apply block offsets; init cursor = offs
    int i = blockIdx.x * SCAN_BLK + threadIdx.x;
    if (i < N_NODES) {
        int o = g_offs[i] + g_bsum[blockIdx.x];
        g_offs[i]   = o;
        g_cursor[i] = o;
    }
}

// ---------------- fused: logits + leaky-relu + exp + denom + CSR scatter ----------------
__global__ void k_logits(const float* __restrict__ edge_attr, const int* __restrict__ ei) {
    __shared__ float we_s[HC];
    if (threadIdx.x < HC) we_s[threadIdx.x] = g_we[threadIdx.x];
    __syncthreads();

    int e = blockIdx.x * blockDim.x + threadIdx.x;
    if (e >= N_EDGES) return;

    // hoisted: slot reservation + alpha gathers issue before the dot-product chain
    int src = ei[e];
    int dst = ei[N_EDGES + e];
    int pos = atomicAdd(&g_cursor[dst], 1);
    float4 al = ((const float4*)g_al)[src];
    float4 ar = ((const float4*)g_ar)[dst];

    const float4* __restrict__ row = (const float4*)(edge_attr + (size_t)e * EDGE_CH);
    const float4* w0 = (const float4*)(we_s);
    const float4* w1 = (const float4*)(we_s + 32);
    const float4* w2 = (const float4*)(we_s + 64);
    const float4* w3 = (const float4*)(we_s + 96);
    float p0 = 0.f, p1 = 0.f, p2 = 0.f, p3 = 0.f;
#pragma unroll
    for (int i = 0; i < 8; i++) {
        float4 v = row[i];
        float4 a0 = w0[i], a1 = w1[i], a2 = w2[i], a3 = w3[i];
        p0 += v.x * a0.x + v.y * a0.y + v.z * a0.z + v.w * a0.w;
        p1 += v.x * a1.x + v.y * a1.y + v.z * a1.z + v.w * a1.w;
        p2 += v.x * a2.x + v.y * a2.y + v.z * a2.z + v.w * a2.w;
        p3 += v.x * a3.x + v.y * a3.y + v.z * a3.z + v.w * a3.w;
    }
    float a0 = al.x + ar.x + p0;
    float a1 = al.y + ar.y + p1;
    float a2 = al.z + ar.z + p2;
    float a3 = al.w + ar.w + p3;
    a0 = (a0 > 0.f) ? a0 : c_neg_slope * a0;
    a1 = (a1 > 0.f) ? a1 : c_neg_slope * a1;
    a2 = (a2 > 0.f) ? a2 : c_neg_slope * a2;
    a3 = (a3 > 0.f) ? a3 : c_neg_slope * a3;
    float4 ex = make_float4(__expf(a0), __expf(a1), __expf(a2), __expf(a3));
    g_csr_src[pos] = src;
    g_csr_ex[pos]  = ex;
    red_add_v4(&g_denom[dst], ex);
}

// ---------------- gather aggregation: one warp per dst node (R4 body, fp32) ----------------
__global__ void k_agg(const float* __restrict__ bias, float* __restrict__ out) {
    const int lane = threadIdx.x & 31;
    const int h    = lane >> 3;                 // head owning this lane's float4
    int node = blockIdx.x * (blockDim.x >> 5) + (threadIdx.x >> 5);
    if (node >= N_NODES) return;

    int beg = g_offs[node];
    int end = g_cursor[node];                   // start + degree
    float4 acc = make_float4(0.f, 0.f, 0.f, 0.f);

    int pos = beg;
    for (; pos + 3 < end; pos += 4) {
        int s0 = g_csr_src[pos];
        int s1 = g_csr_src[pos + 1];
        int s2 = g_csr_src[pos + 2];
        int s3 = g_csr_src[pos + 3];
        float a0 = ((const float*)g_csr_ex)[(size_t)pos * 4 + h];
        float a1 = ((const float*)g_csr_ex)[(size_t)(pos + 1) * 4 + h];
        float a2 = ((const float*)g_csr_ex)[(size_t)(pos + 2) * 4 + h];
        float a3 = ((const float*)g_csr_ex)[(size_t)(pos + 3) * 4 + h];
        float4 v0 = ((const float4*)g_xl)[(size_t)s0 * 32 + lane];
        float4 v1 = ((const float4*)g_xl)[(size_t)s1 * 32 + lane];
        float4 v2 = ((const float4*)g_xl)[(size_t)s2 * 32 + lane];
        float4 v3 = ((const float4*)g_xl)[(size_t)s3 * 32 + lane];
        acc.x += a0 * v0.x + a1 * v1.x + a2 * v2.x + a3 * v3.x;
        acc.y += a0 * v0.y + a1 * v1.y + a2 * v2.y + a3 * v3.y;
        acc.z += a0 * v0.z + a1 * v1.z + a2 * v2.z + a3 * v3.z;
        acc.w += a0 * v0.w + a1 * v1.w + a2 * v2.w + a3 * v3.w;
    }
    for (; pos < end; pos++) {
        int s0 = g_csr_src[pos];
        float a0 = ((const float*)g_csr_ex)[(size_t)pos * 4 + h];
        float4 v0 = ((const float4*)g_xl)[(size_t)s0 * 32 + lane];
        acc.x += a0 * v0.x; acc.y += a0 * v0.y; acc.z += a0 * v0.z; acc.w += a0 * v0.w;
    }
    float inv = 1.0f / (((const float*)g_denom)[(size_t)node * 4 + h] + 1e-16f);
    float4 b = ((const float4*)bias)[lane];
    acc.x = acc.x * inv + b.x;
    acc.y = acc.y * inv + b.y;
    acc.z = acc.z * inv + b.z;
    acc.w = acc.w * inv + b.w;
    ((float4*)out)[(size_t)node * 32 + lane] = acc;
}

// ---------------- launch: R13 schedule; k_gemm enqueued 4th so ncu profiles it ----------------
extern "C" void kernel_launch(void* const* d_in, const int* in_sizes, int n_in,
                              void* d_out, int out_size) {
    const float* x         = (const float*)d_in[0];
    const float* edge_attr = (const float*)d_in[1];
    const float* Wl        = (const float*)d_in[2];
    const float* We        = (const float*)d_in[3];
    const float* att_l     = (const float*)d_in[4];
    const float* att_r     = (const float*)d_in[5];
    const float* att_e     = (const float*)d_in[6];
    const float* bias      = (const float*)d_in[7];
    const int*   ei        = (const int*)d_in[8];
    float* out = (float*)d_out;

    cudaFuncSetAttribute(k_gemm, cudaFuncAttributeMaxDynamicSharedMemorySize, GEMM_SMEM);

    cudaStream_t sA, sB;
    cudaStreamCreateWithFlags(&sA, cudaStreamNonBlocking);
    cudaStreamCreateWithFlags(&sB, cudaStreamNonBlocking);
    cudaEvent_t evRoot, evA, evB;
    cudaEventCreateWithFlags(&evRoot, cudaEventDisableTiming);
    cudaEventCreateWithFlags(&evA,    cudaEventDisableTiming);
    cudaEventCreateWithFlags(&evB,    cudaEventDisableTiming);

    cudaEventRecord(evRoot, 0);
    cudaStreamWaitEvent(sA, evRoot, 0);
    cudaStreamWaitEvent(sB, evRoot, 0);

    // Branch A part 1 (sA): launches 0-2
    k_zero <<<(N_NODES * HEADS + 255) / 256, 256, 0, sA>>>();
    k_hist <<<(N_EDGES / 4 + 255) / 256, 256, 0, sA>>>(ei);
    k_scan1<<<SCAN_NB, SCAN_BLK, 0, sA>>>();

    // Main stream: GEMM enqueued as launch #3 (4th) -> lands in the ncu capture slot
    k_gemm<<<GEMM_BLOCKS, 128, GEMM_SMEM>>>(x, Wl, att_l, att_r);

    // Branch A part 2 (sA)
    k_scan2<<<1, 128, 0, sA>>>();
    k_scan3<<<SCAN_NB, SCAN_BLK, 0, sA>>>();
    cudaEventRecord(evA, sA);

    // Branch B (sB): tiny weight fold
    k_wepre<<<1, 128, 0, sB>>>(We, att_e);
    cudaEventRecord(evB, sB);

    // join
    cudaStreamWaitEvent(0, evA, 0);
    cudaStreamWaitEvent(0, evB, 0);

    k_logits<<<(N_EDGES + 255) / 256, 256>>>(edge_attr, ei);
    k_agg<<<(N_NODES * 32 + 255) / 256, 256>>>(bias, out);

    cudaEventDestroy(evRoot);
    cudaEventDestroy(evA);
    cudaEventDestroy(evB);
    cudaStreamDestroy(sA);
    cudaStreamDestroy(sB);
}

// round 15
// speedup vs baseline: 1.6013x; 1.2100x over previous
#include <cuda_runtime.h>
#include <cstdint>

#define N_NODES 100000
#define N_EDGES 1600000
#define HC 128            // HEADS * OUT_CH
#define HEADS 4
#define OUT_CH 32
#define EDGE_CH 32
#define SCAN_BLK 1024
#define SCAN_NB ((N_NODES + SCAN_BLK - 1) / SCAN_BLK)   // 98
#define GEMM_BLOCKS 296
#define GEMM_SMEM ((128 * 33 + 32 * 33) * 16)           // 84480 bytes

__constant__ float c_neg_slope = 0.2f;

// ---------------- scratch (static device globals; no allocation) ----------------
__device__ float  g_xl[(size_t)N_NODES * HC];   // 51.2 MB projected node features
__device__ float  g_al[N_NODES * HEADS];        // alpha_l per node/head
__device__ float  g_ar[N_NODES * HEADS];        // alpha_r per node/head
__device__ float  g_we[HC];                     // folded We^T * att_e  [H][32]
__device__ float4 g_denom[N_NODES];             // softmax denominators (sum of ex)
__device__ int    g_hist[N_NODES];              // in-degree histogram
__device__ int    g_offs[N_NODES];              // CSR start offsets (exclusive scan)
__device__ int    g_cursor[N_NODES];            // scatter cursors
__device__ int    g_bsum[SCAN_NB];              // scan block sums
__device__ int    g_csr_src[N_EDGES];           // dst-sorted source node ids
__device__ float4 g_csr_ex[N_EDGES];            // dst-sorted UNnormalized exp(logit)

// vectorized 16B global reduction (sm_90+)
__device__ __forceinline__ void red_add_v4(float4* p, float4 v) {
    asm volatile("red.global.add.v4.f32 [%0], {%1, %2, %3, %4};"
                 :: "l"(p), "f"(v.x), "f"(v.y), "f"(v.z), "f"(v.w)
                 : "memory");
}

// ---------------- zero hist + denom ----------------
__global__ void k_zero() {
    int idx = blockIdx.x * blockDim.x + threadIdx.x;
    if (idx < N_NODES * HEADS) ((float*)g_denom)[idx] = 0.0f;
    if (idx < N_NODES) g_hist[idx] = 0;
}

// ---------------- fold We with att_e  ->  g_we[h*32+k] ----------------
__global__ void k_wepre(const float* __restrict__ We, const float* __restrict__ att_e) {
    int t = threadIdx.x;           // 0..127  = h*32 + k
    int h = t >> 5, k = t & 31;
    float s = 0.0f;
#pragma unroll
    for (int c = 0; c < OUT_CH; c++)
        s += We[(h * OUT_CH + c) * EDGE_CH + k] * att_e[h * OUT_CH + c];
    g_we[t] = s;
}

// ---------------- in-degree histogram (dst only, int4 vectorized) ----------------
__global__ void k_hist(const int* __restrict__ ei) {
    int i = blockIdx.x * blockDim.x + threadIdx.x;   // quad index
    if (i * 4 >= N_EDGES) return;
    int4 d = ((const int4*)(ei + N_EDGES))[i];
    atomicAdd(&g_hist[d.x], 1);
    atomicAdd(&g_hist[d.y], 1);
    atomicAdd(&g_hist[d.z], 1);
    atomicAdd(&g_hist[d.w], 1);
}

// ---------------- register-blocked GEMM: xl = x @ Wl^T, fused alpha_l / alpha_r ----------------
// Thread tile 4 nodes x 8 cols. CONFLICT-FREE mapping: phase-mates (tn=0..7) read ADJACENT
// x rows (row stride 33 float4 = 132 floats = 4 banks) -> 8 distinct bank groups.
// wv loads are phase-uniform broadcasts. Per k4: 12 LDS.128 -> 128 FMA, smem no longer binding.
__global__ __launch_bounds__(128, 2) void k_gemm(const float* __restrict__ x,
                                                 const float* __restrict__ Wl,
                                                 const float* __restrict__ att_l,
                                                 const float* __restrict__ att_r) {
    extern __shared__ float4 smem4[];
    float4* ws4 = smem4;                 // [128 cols][33]  (32 used + 1 pad)
    float4* xs4 = smem4 + 128 * 33;      // [32 nodes][33]

    const int tid      = threadIdx.x;
    const int lane     = tid & 31;
    const int w        = tid >> 5;       // warp index == head
    const int tc_local = lane >> 3;      // 0..3  (== LDS phase id)
    const int tn       = lane & 7;       // 0..7 (node within phase)
    const int tc       = w * 4 + tc_local;  // 0..15 (col group of 8)

    float attl[8], attr[8];
#pragma unroll
    for (int i = 0; i < 8; i++) {
        attl[i] = att_l[tc * 8 + i];
        attr[i] = att_r[tc * 8 + i];
    }

    // stage all of Wl: 4096 float4, coalesced reads, conflict-free padded writes
    for (int idx = tid; idx < 128 * 32; idx += 128) {
        int col = idx >> 5, kq = idx & 31;
        ws4[col * 33 + kq] = ((const float4*)Wl)[idx];
    }

    for (int base = blockIdx.x * 32; base < N_NODES; base += gridDim.x * 32) {
        __syncthreads();    // xs4 free (and first-iter: ws4 staged)
        for (int idx = tid; idx < 32 * 32; idx += 128) {
            int nn = idx >> 5, kq = idx & 31;
            xs4[nn * 33 + kq] = ((const float4*)x)[(size_t)(base + nn) * 32 + kq];
        }
        __syncthreads();

        float acc[4][8];
#pragma unroll
        for (int n = 0; n < 4; n++)
#pragma unroll
            for (int i = 0; i < 8; i++) acc[n][i] = 0.f;

#pragma unroll 2
        for (int kq = 0; kq < 32; kq++) {
            float4 xv[4], wv[8];
#pragma unroll
            for (int n = 0; n < 4; n++) xv[n] = xs4[(n * 8 + tn) * 33 + kq];   // stride-1 rows
#pragma unroll
            for (int i = 0; i < 8; i++) wv[i] = ws4[(tc * 8 + i) * 33 + kq];   // phase broadcast
#pragma unroll
            for (int n = 0; n < 4; n++)
#pragma unroll
                for (int i = 0; i < 8; i++)
                    acc[n][i] += xv[n].x * wv[i].x + xv[n].y * wv[i].y
                               + xv[n].z * wv[i].z + xv[n].w * wv[i].w;
        }

#pragma unroll
        for (int n = 0; n < 4; n++) {
            int node = base + n * 8 + tn;
            float4 lo = make_float4(acc[n][0], acc[n][1], acc[n][2], acc[n][3]);
            float4 hi = make_float4(acc[n][4], acc[n][5], acc[n][6], acc[n][7]);
            ((float4*)g_xl)[(size_t)node * 32 + tc * 2]     = lo;
            ((float4*)g_xl)[(size_t)node * 32 + tc * 2 + 1] = hi;
            float pl = 0.f, pr = 0.f;
#pragma unroll
            for (int i = 0; i < 8; i++) {
                pl += acc[n][i] * attl[i];
                pr += acc[n][i] * attr[i];
            }
            pl += __shfl_down_sync(0xffffffffu, pl, 16);
            pl += __shfl_down_sync(0xffffffffu, pl, 8);
            pr += __shfl_down_sync(0xffffffffu, pr, 16);
            pr += __shfl_down_sync(0xffffffffu, pr, 8);
            if (tc_local == 0) {
                g_al[node * HEADS + w] = pl;
                g_ar[node * HEADS + w] = pr;
            }
        }
    }
}

// ---------------- scan kernels: exclusive prefix over g_hist -> g_offs ----------------
__global__ void k_scan1() {
    __shared__ int wsum[32];
    int i = blockIdx.x * SCAN_BLK + threadIdx.x;
    int lane = threadIdx.x & 31, wid = threadIdx.x >> 5;
    int v = (i < N_NODES) ? g_hist[i] : 0;
    int inc = v;
#pragma unroll
    for (int off = 1; off < 32; off <<= 1) {
        int t = __shfl_up_sync(0xffffffffu, inc, off);
        if (lane >= off) inc += t;
    }
    if (lane == 31) wsum[wid] = inc;
    __syncthreads();
    if (wid == 0) {
        int s = wsum[lane];
#pragma unroll
        for (int off = 1; off < 32; off <<= 1) {
            int t = __shfl_up_sync(0xffffffffu, s, off);
            if (lane >= off) s += t;
        }
        wsum[lane] = s;
    }
    __syncthreads();
    int base = (wid > 0) ? wsum[wid - 1] : 0;
    if (i < N_NODES) g_offs[i] = base + inc - v;
    if (threadIdx.x == SCAN_BLK - 1) g_bsum[blockIdx.x] = base + inc;
}

__global__ void k_scan2() {   // single block, scan SCAN_NB (=98) block totals, exclusive
    __shared__ int wsum[4];
    int lane = threadIdx.x & 31, wid = threadIdx.x >> 5;
    int v = (threadIdx.x < SCAN_NB) ? g_bsum[threadIdx.x] : 0;
    int inc = v;
#pragma unroll
    for (int off = 1; off < 32; off <<= 1) {
        int t = __shfl_up_sync(0xffffffffu, inc, off);
        if (lane >= off) inc += t;
    }
    if (lane == 31) wsum[wid] = inc;
    __syncthreads();
    int base = 0;
    for (int w = 0; w < wid; w++) base += wsum[w];
    if (threadIdx.x < SCAN_NB) g_bsum[threadIdx.x] = base + inc - v;
}

__global__ void k_scan3() {   // apply block offsets; init cursor = offs
    int i = blockIdx.x * SCAN_BLK + threadIdx.x;
    if (i < N_NODES) {
        int o = g_offs[i] + g_bsum[blockIdx.x];
        g_offs[i]   = o;
        g_cursor[i] = o;
    }
}

// ---------------- fused: logits + leaky-relu + exp + denom + CSR scatter ----------------
__global__ void k_logits(const float* __restrict__ edge_attr, const int* __restrict__ ei) {
    __shared__ float we_s[HC];
    if (threadIdx.x < HC) we_s[threadIdx.x] = g_we[threadIdx.x];
    __syncthreads();

    int e = blockIdx.x * blockDim.x + threadIdx.x;
    if (e >= N_EDGES) return;

    // hoisted: slot reservation + alpha gathers issue before the dot-product chain
    int src = ei[e];
    int dst = ei[N_EDGES + e];
    int pos = atomicAdd(&g_cursor[dst], 1);
    float4 al = ((const float4*)g_al)[src];
    float4 ar = ((const float4*)g_ar)[dst];

    const float4* __restrict__ row = (const float4*)(edge_attr + (size_t)e * EDGE_CH);
    const float4* w0 = (const float4*)(we_s);
    const float4* w1 = (const float4*)(we_s + 32);
    const float4* w2 = (const float4*)(we_s + 64);
    const float4* w3 = (const float4*)(we_s + 96);
    float p0 = 0.f, p1 = 0.f, p2 = 0.f, p3 = 0.f;
#pragma unroll
    for (int i = 0; i < 8; i++) {
        float4 v = row[i];
        float4 a0 = w0[i], a1 = w1[i], a2 = w2[i], a3 = w3[i];
        p0 += v.x * a0.x + v.y * a0.y + v.z * a0.z + v.w * a0.w;
        p1 += v.x * a1.x + v.y * a1.y + v.z * a1.z + v.w * a1.w;
        p2 += v.x * a2.x + v.y * a2.y + v.z * a2.z + v.w * a2.w;
        p3 += v.x * a3.x + v.y * a3.y + v.z * a3.z + v.w * a3.w;
    }
    float a0 = al.x + ar.x + p0;
    float a1 = al.y + ar.y + p1;
    float a2 = al.z + ar.z + p2;
    float a3 = al.w + ar.w + p3;
    a0 = (a0 > 0.f) ? a0 : c_neg_slope * a0;
    a1 = (a1 > 0.f) ? a1 : c_neg_slope * a1;
    a2 = (a2 > 0.f) ? a2 : c_neg_slope * a2;
    a3 = (a3 > 0.f) ? a3 : c_neg_slope * a3;
    float4 ex = make_float4(__expf(a0), __expf(a1), __expf(a2), __expf(a3));
    g_csr_src[pos] = src;
    g_csr_ex[pos]  = ex;
    red_add_v4(&g_denom[dst], ex);
}

// ---------------- gather aggregation: one warp per dst node (R4 body, fp32) ----------------
__global__ void k_agg(const float* __restrict__ bias, float* __restrict__ out) {
    const int lane = threadIdx.x & 31;
    const int h    = lane >> 3;                 // head owning this lane's float4
    int node = blockIdx.x * (blockDim.x >> 5) + (threadIdx.x >> 5);
    if (node >= N_NODES) return;

    int beg = g_offs[node];
    int end = g_cursor[node];                   // start + degree
    float4 acc = make_float4(0.f, 0.f, 0.f, 0.f);

    int pos = beg;
    for (; pos + 3 < end; pos += 4) {
        int s0 = g_csr_src[pos];
        int s1 = g_csr_src[pos + 1];
        int s2 = g_csr_src[pos + 2];
        int s3 = g_csr_src[pos + 3];
        float a0 = ((const float*)g_csr_ex)[(size_t)pos * 4 + h];
        float a1 = ((const float*)g_csr_ex)[(size_t)(pos + 1) * 4 + h];
        float a2 = ((const float*)g_csr_ex)[(size_t)(pos + 2) * 4 + h];
        float a3 = ((const float*)g_csr_ex)[(size_t)(pos + 3) * 4 + h];
        float4 v0 = ((const float4*)g_xl)[(size_t)s0 * 32 + lane];
        float4 v1 = ((const float4*)g_xl)[(size_t)s1 * 32 + lane];
        float4 v2 = ((const float4*)g_xl)[(size_t)s2 * 32 + lane];
        float4 v3 = ((const float4*)g_xl)[(size_t)s3 * 32 + lane];
        acc.x += a0 * v0.x + a1 * v1.x + a2 * v2.x + a3 * v3.x;
        acc.y += a0 * v0.y + a1 * v1.y + a2 * v2.y + a3 * v3.y;
        acc.z += a0 * v0.z + a1 * v1.z + a2 * v2.z + a3 * v3.z;
        acc.w += a0 * v0.w + a1 * v1.w + a2 * v2.w + a3 * v3.w;
    }
    for (; pos < end; pos++) {
        int s0 = g_csr_src[pos];
        float a0 = ((const float*)g_csr_ex)[(size_t)pos * 4 + h];
        float4 v0 = ((const float4*)g_xl)[(size_t)s0 * 32 + lane];
        acc.x += a0 * v0.x; acc.y += a0 * v0.y; acc.z += a0 * v0.z; acc.w += a0 * v0.w;
    }
    float inv = 1.0f / (((const float*)g_denom)[(size_t)node * 4 + h] + 1e-16f);
    float4 b = ((const float4*)bias)[lane];
    acc.x = acc.x * inv + b.x;
    acc.y = acc.y * inv + b.y;
    acc.z = acc.z * inv + b.z;
    acc.w = acc.w * inv + b.w;
    ((float4*)out)[(size_t)node * 32 + lane] = acc;
}

// ---------------- launch: R13 schedule; k_gemm enqueued 4th so ncu profiles it ----------------
extern "C" void kernel_launch(void* const* d_in, const int* in_sizes, int n_in,
                              void* d_out, int out_size) {
    const float* x         = (const float*)d_in[0];
    const float* edge_attr = (const float*)d_in[1];
    const float* Wl        = (const float*)d_in[2];
    const float* We        = (const float*)d_in[3];
    const float* att_l     = (const float*)d_in[4];
    const float* att_r     = (const float*)d_in[5];
    const float* att_e     = (const float*)d_in[6];
    const float* bias      = (const float*)d_in[7];
    const int*   ei        = (const int*)d_in[8];
    float* out = (float*)d_out;

    cudaFuncSetAttribute(k_gemm, cudaFuncAttributeMaxDynamicSharedMemorySize, GEMM_SMEM);

    cudaStream_t sA, sB;
    cudaStreamCreateWithFlags(&sA, cudaStreamNonBlocking);
    cudaStreamCreateWithFlags(&sB, cudaStreamNonBlocking);
    cudaEvent_t evRoot, evA, evB;
    cudaEventCreateWithFlags(&evRoot, cudaEventDisableTiming);
    cudaEventCreateWithFlags(&evA,    cudaEventDisableTiming);
    cudaEventCreateWithFlags(&evB,    cudaEventDisableTiming);

    cudaEventRecord(evRoot, 0);
    cudaStreamWaitEvent(sA, evRoot, 0);
    cudaStreamWaitEvent(sB, evRoot, 0);

    // Branch A part 1 (sA): launches 0-2
    k_zero <<<(N_NODES * HEADS + 255) / 256, 256, 0, sA>>>();
    k_hist <<<(N_EDGES / 4 + 255) / 256, 256, 0, sA>>>(ei);
    k_scan1<<<SCAN_NB, SCAN_BLK, 0, sA>>>();

    // Main stream: GEMM enqueued as launch #3 (4th) -> lands in the ncu capture slot
    k_gemm<<<GEMM_BLOCKS, 128, GEMM_SMEM>>>(x, Wl, att_l, att_r);

    // Branch A part 2 (sA)
    k_scan2<<<1, 128, 0, sA>>>();
    k_scan3<<<SCAN_NB, SCAN_BLK, 0, sA>>>();
    cudaEventRecord(evA, sA);

    // Branch B (sB): tiny weight fold
    k_wepre<<<1, 128, 0, sB>>>(We, att_e);
    cudaEventRecord(evB, sB);

    // join
    cudaStreamWaitEvent(0, evA, 0);
    cudaStreamWaitEvent(0, evB, 0);

    k_logits<<<(N_EDGES + 255) / 256, 256>>>(edge_attr, ei);
    k_agg<<<(N_NODES * 32 + 255) / 256, 256>>>(bias, out);

    cudaEventDestroy(evRoot);
    cudaEventDestroy(evA);
    cudaEventDestroy(evB);
    cudaStreamDestroy(sA);
    cudaStreamDestroy(sB);
}